// round 10
// baseline (speedup 1.0000x reference)
#include <cuda_runtime.h>
#include <cuda_bf16.h>
#include <cstdint>

// Problem constants
#define BB 2
#define TT 2048
#define DM 1024
#define NH 16
#define HD 64
#define MROWS (BB * TT)          // 4096
#define NELEM_X (MROWS * DM)     // 4194304
#define NELEM_W (DM * DM)        // 1048576

// ---------------- scratch (no allocation allowed) ----------------
__device__ __nv_bfloat16 g_qhi[NELEM_X], g_qlo[NELEM_X];
__device__ __nv_bfloat16 g_khi[NELEM_X], g_klo[NELEM_X];
__device__ __nv_bfloat16 g_vhi[NELEM_X], g_vlo[NELEM_X];
__device__ __nv_bfloat16 g_ahi[NELEM_X], g_alo[NELEM_X];
__device__ __nv_bfloat16 g_xhi[NELEM_X], g_xlo[NELEM_X];
__device__ __nv_bfloat16 g_whi[4][NELEM_W], g_wlo[4][NELEM_W];

// ---------------- helpers ----------------
__device__ __forceinline__ uint32_t smem_u32(const void* p) {
    uint32_t a;
    asm("{ .reg .u64 t; cvta.to.shared.u64 t, %1; cvt.u32.u64 %0, t; }" : "=r"(a) : "l"(p));
    return a;
}
__device__ __forceinline__ void cp_async16(uint32_t saddr, const void* gptr) {
    asm volatile("cp.async.cg.shared.global [%0], [%1], 16;" :: "r"(saddr), "l"(gptr));
}
__device__ __forceinline__ void ldsm4(uint32_t* r, uint32_t addr) {
    asm volatile("ldmatrix.sync.aligned.m8n8.x4.shared.b16 {%0,%1,%2,%3}, [%4];"
                 : "=r"(r[0]), "=r"(r[1]), "=r"(r[2]), "=r"(r[3]) : "r"(addr));
}
__device__ __forceinline__ void ldsm2(uint32_t* r, uint32_t addr) {
    asm volatile("ldmatrix.sync.aligned.m8n8.x2.shared.b16 {%0,%1}, [%2];"
                 : "=r"(r[0]), "=r"(r[1]) : "r"(addr));
}
__device__ __forceinline__ void ldsm2t(uint32_t* r, uint32_t addr) {
    asm volatile("ldmatrix.sync.aligned.m8n8.x2.trans.shared.b16 {%0,%1}, [%2];"
                 : "=r"(r[0]), "=r"(r[1]) : "r"(addr));
}
__device__ __forceinline__ void mma16816(float* d, const uint32_t* a, const uint32_t* b) {
    asm volatile("mma.sync.aligned.m16n8k16.row.col.f32.bf16.bf16.f32 "
                 "{%0,%1,%2,%3},{%4,%5,%6,%7},{%8,%9},{%0,%1,%2,%3};"
                 : "+f"(d[0]), "+f"(d[1]), "+f"(d[2]), "+f"(d[3])
                 : "r"(a[0]), "r"(a[1]), "r"(a[2]), "r"(a[3]), "r"(b[0]), "r"(b[1]));
}
__device__ __forceinline__ void split_pack(float a, float b, uint32_t& hp, uint32_t& lp) {
    __nv_bfloat16 ha = __float2bfloat16(a), hb = __float2bfloat16(b);
    __nv_bfloat16 la = __float2bfloat16(a - __bfloat162float(ha));
    __nv_bfloat16 lb = __float2bfloat16(b - __bfloat162float(hb));
    hp = ((uint32_t)__bfloat16_as_ushort(hb) << 16) | __bfloat16_as_ushort(ha);
    lp = ((uint32_t)__bfloat16_as_ushort(lb) << 16) | __bfloat16_as_ushort(la);
}

// ---------------- fused split of x + 4 weight matrices ----------------
__global__ __launch_bounds__(256) void split5_kernel(
    const float* __restrict__ x,
    const float* __restrict__ w0, const float* __restrict__ w1,
    const float* __restrict__ w2, const float* __restrict__ w3,
    __nv_bfloat16* __restrict__ xhi, __nv_bfloat16* __restrict__ xlo,
    __nv_bfloat16* __restrict__ whi, __nv_bfloat16* __restrict__ wlo) {
    const int blk = blockIdx.x;
    const float* in;
    __nv_bfloat16 *hi, *lo;
    int i;
    if (blk < 4096) {
        in = x; hi = xhi; lo = xlo;
        i = blk * 256 + threadIdx.x;
    } else {
        int wblk = blk - 4096;
        int w = wblk >> 10;
        const float* ws[4] = {w0, w1, w2, w3};
        in = ws[w];
        hi = whi + (size_t)w * NELEM_W;
        lo = wlo + (size_t)w * NELEM_W;
        i = (wblk & 1023) * 256 + threadIdx.x;
    }
    float4 v = reinterpret_cast<const float4*>(in)[i];
    uint32_t h0, l0, h1, l1;
    split_pack(v.x, v.y, h0, l0);
    split_pack(v.z, v.w, h1, l1);
    uint32_t* hp = reinterpret_cast<uint32_t*>(hi);
    uint32_t* lp = reinterpret_cast<uint32_t*>(lo);
    hp[2 * i + 0] = h0; hp[2 * i + 1] = h1;
    lp[2 * i + 0] = l0; lp[2 * i + 1] = l1;
}

// ---------------- mma.sync bf16x3 GEMM (unchanged from R7) --------------
#define GKC 64
#define ROWB 144
#define BUFB (128 * ROWB)            // 18432
#define STGB (4 * BUFB)              // 73728
#define GSMEM (3 * STGB)             // 221184

template<bool SPLITOUT>
__global__ __launch_bounds__(256) void gemm_mma(const __nv_bfloat16* __restrict__ Ahi,
                                                const __nv_bfloat16* __restrict__ Alo,
                                                const __nv_bfloat16* __restrict__ Bhi,
                                                const __nv_bfloat16* __restrict__ Blo,
                                                float* __restrict__ C,
                                                __nv_bfloat16* __restrict__ Chi,
                                                __nv_bfloat16* __restrict__ Clo,
                                                int M, int N, int K) {
    extern __shared__ char smem[];
    const uint32_t sbase = smem_u32(smem);
    const int tid = threadIdx.x;
    const int wid = tid >> 5;
    const int lane = tid & 31;
    const int warp_m = (wid & 1) * 64;
    const int warp_n = (wid >> 1) * 32;
    const int rowBase = blockIdx.y * 128;
    const int colBase = blockIdx.x * 128;

    const __nv_bfloat16* srcs[4];
    srcs[0] = Ahi + (size_t)rowBase * K;
    srcs[1] = Alo + (size_t)rowBase * K;
    srcs[2] = Bhi + (size_t)colBase * K;
    srcs[3] = Blo + (size_t)colBase * K;

    float acc[16][4];
#pragma unroll
    for (int i = 0; i < 16; i++)
#pragma unroll
        for (int j = 0; j < 4; j++) acc[i][j] = 0.0f;

    const int NCH = K / GKC;   // 16

    auto issue = [&](int chunk) {
        const uint32_t stb = sbase + (uint32_t)(chunk % 3) * STGB;
        const int k0 = chunk * GKC;
#pragma unroll
        for (int t = 0; t < 16; t++) {
            int idx = tid + t * 256;
            int b = idx >> 10;
            int pos = idx & 1023;
            int r = pos >> 3;
            int c8 = pos & 7;
            cp_async16(stb + (uint32_t)b * BUFB + (uint32_t)(r * ROWB + c8 * 16),
                       srcs[b] + (size_t)r * K + k0 + c8 * 8);
        }
        asm volatile("cp.async.commit_group;" ::: "memory");
    };

    issue(0);
    issue(1);
    for (int i = 0; i < NCH; i++) {
        if (i + 1 < NCH) {
            asm volatile("cp.async.wait_group 1;" ::: "memory");
        } else {
            asm volatile("cp.async.wait_group 0;" ::: "memory");
        }
        __syncthreads();
        if (i + 2 < NCH) issue(i + 2);

        const uint32_t stb = sbase + (uint32_t)(i % 3) * STGB;
        const int lm = lane & 15, lk = lane >> 4;
        const int ln = lane & 7, lkb = (lane >> 3) & 1;
#pragma unroll
        for (int ks = 0; ks < 4; ks++) {
            uint32_t ah[4][4], al[4][4], bh[4][2], bl[4][2];
#pragma unroll
            for (int mt = 0; mt < 4; mt++) {
                uint32_t ra = stb + (uint32_t)((warp_m + mt * 16 + lm) * ROWB + ks * 32 + lk * 16);
                ldsm4(ah[mt], ra);
                ldsm4(al[mt], ra + BUFB);
            }
#pragma unroll
            for (int nt = 0; nt < 4; nt++) {
                uint32_t rb = stb + 2 * BUFB + (uint32_t)((warp_n + nt * 8 + ln) * ROWB + ks * 32 + lkb * 16);
                ldsm2(bh[nt], rb);
                ldsm2(bl[nt], rb + BUFB);
            }
#pragma unroll
            for (int mt = 0; mt < 4; mt++)
#pragma unroll
                for (int nt = 0; nt < 4; nt++) {
                    mma16816(acc[mt * 4 + nt], ah[mt], bh[nt]);
                    mma16816(acc[mt * 4 + nt], ah[mt], bl[nt]);
                    mma16816(acc[mt * 4 + nt], al[mt], bh[nt]);
                }
        }
    }

    const int mrow = rowBase + warp_m + (lane >> 2);
    const int ncol = colBase + warp_n + (lane & 3) * 2;
#pragma unroll
    for (int mt = 0; mt < 4; mt++)
#pragma unroll
        for (int nt = 0; nt < 4; nt++) {
            const float* a = acc[mt * 4 + nt];
            size_t p0 = (size_t)(mrow + mt * 16) * N + ncol + nt * 8;
            size_t p1 = p0 + 8 * (size_t)N;
            if (!SPLITOUT) {
                *reinterpret_cast<float2*>(C + p0) = make_float2(a[0], a[1]);
                *reinterpret_cast<float2*>(C + p1) = make_float2(a[2], a[3]);
            } else {
                uint32_t hp, lp;
                split_pack(a[0], a[1], hp, lp);
                *reinterpret_cast<uint32_t*>(Chi + p0) = hp;
                *reinterpret_cast<uint32_t*>(Clo + p0) = lp;
                split_pack(a[2], a[3], hp, lp);
                *reinterpret_cast<uint32_t*>(Chi + p1) = hp;
                *reinterpret_cast<uint32_t*>(Clo + p1) = lp;
            }
        }
}

// ---------------- Flash attention via mma.sync (causal) ----------------
// Br=128, Bc=64, D=64. 8 warps, warp-local softmax. bf16x3 QK^T and PV.
// 2 KV stages (108KB smem) -> 2 CTAs/SM. Long CTAs (high qt) scheduled first.
#define FBR 128
#define FBC 64
#define FROWB 144
#define QBUF (FBR * FROWB)           // 18432
#define KVBUF (FBC * FROWB)          // 9216
#define FKV0 (2 * QBUF)              // 36864
#define FSTG (4 * KVBUF)             // 36864
#define FSMEM2 (FKV0 + 2 * FSTG)     // 110592

__global__ __launch_bounds__(256, 2) void flash_mma(
    const __nv_bfloat16* __restrict__ qh, const __nv_bfloat16* __restrict__ ql,
    const __nv_bfloat16* __restrict__ kh, const __nv_bfloat16* __restrict__ kl,
    const __nv_bfloat16* __restrict__ vh, const __nv_bfloat16* __restrict__ vl,
    __nv_bfloat16* __restrict__ oh, __nv_bfloat16* __restrict__ ol) {
    extern __shared__ char smem[];
    const uint32_t sbase = smem_u32(smem);
    const int tid = threadIdx.x;
    const int wid = tid >> 5;
    const int lane = tid & 31;
    const int qt = gridDim.x - 1 - blockIdx.x;   // long CTAs first
    const int bh = blockIdx.y;
    const int b = bh >> 4, h = bh & 15;
    const size_t base = (size_t)b * TT * DM + h * HD;
    const int q0 = qt * FBR;

    const __nv_bfloat16* mats[4] = {kh, kl, vh, vl};
    auto issue_kv_nocommit = [&](int kt) {
        const uint32_t stb = sbase + FKV0 + (uint32_t)(kt & 1) * FSTG;
        const int t0 = kt * FBC;
#pragma unroll
        for (int t = 0; t < 8; t++) {
            int idx = tid + t * 256;
            int mat = idx >> 9;
            int pos = idx & 511;
            int r = pos >> 3, c8 = pos & 7;
            cp_async16(stb + (uint32_t)(mat * KVBUF + r * FROWB + c8 * 16),
                       mats[mat] + base + (size_t)(t0 + r) * DM + c8 * 8);
        }
    };

    // group 0: Q (hi/lo) + KV tile 0
#pragma unroll
    for (int t = 0; t < 8; t++) {
        int idx = tid + t * 256;
        int mat = idx >> 10;
        int pos = idx & 1023;
        int r = pos >> 3, c8 = pos & 7;
        const __nv_bfloat16* src = (mat ? ql : qh) + base + (size_t)(q0 + r) * DM + c8 * 8;
        cp_async16(sbase + (uint32_t)(mat * QBUF + r * FROWB + c8 * 16), src);
    }
    issue_kv_nocommit(0);
    asm volatile("cp.async.commit_group;" ::: "memory");

    uint32_t qfh[4][4];
    float m0 = -1e30f, m1 = -1e30f, l0 = 0.0f, l1 = 0.0f;
    float oacc[8][4];
#pragma unroll
    for (int i = 0; i < 8; i++)
#pragma unroll
        for (int j = 0; j < 4; j++) oacc[i][j] = 0.0f;

    const int NKT = 2 * (qt + 1);
    for (int kt = 0; kt < NKT; kt++) {
        if (kt + 1 < NKT) {
            issue_kv_nocommit(kt + 1);
            asm volatile("cp.async.commit_group;" ::: "memory");
            asm volatile("cp.async.wait_group 1;" ::: "memory");
        } else {
            asm volatile("cp.async.wait_group 0;" ::: "memory");
        }
        __syncthreads();
        if (kt == 0) {
            // Q hi fragments persistent; lo reloaded per tile
#pragma unroll
            for (int ks = 0; ks < 4; ks++) {
                uint32_t a = sbase + (uint32_t)((wid * 16 + (lane & 15)) * FROWB + ks * 32 + (lane >> 4) * 16);
                ldsm4(qfh[ks], a);
            }
        }
        const uint32_t stb = sbase + FKV0 + (uint32_t)(kt & 1) * FSTG;

        // S = Q K^T (bf16x3)
        float s[8][4];
#pragma unroll
        for (int i = 0; i < 8; i++)
#pragma unroll
            for (int j = 0; j < 4; j++) s[i][j] = 0.0f;
#pragma unroll
        for (int ks = 0; ks < 4; ks++) {
            uint32_t qfl[4];
            {
                uint32_t a = sbase + QBUF + (uint32_t)((wid * 16 + (lane & 15)) * FROWB + ks * 32 + (lane >> 4) * 16);
                ldsm4(qfl, a);
            }
#pragma unroll
            for (int nt = 0; nt < 8; nt++) {
                uint32_t a = stb + (uint32_t)((nt * 8 + (lane & 7)) * FROWB + ks * 32 + ((lane >> 3) & 1) * 16);
                uint32_t kh2[2], kl2[2];
                ldsm2(kh2, a);
                ldsm2(kl2, a + KVBUF);
                mma16816(s[nt], qfh[ks], kh2);
                mma16816(s[nt], qfh[ks], kl2);
                mma16816(s[nt], qfl, kh2);
            }
        }

        // scale + causal mask
        const int r0g = q0 + wid * 16 + (lane >> 2);
        const bool need_mask = (kt >= 2 * qt);
#pragma unroll
        for (int nt = 0; nt < 8; nt++)
#pragma unroll
            for (int c = 0; c < 4; c++) {
                float val = s[nt][c] * 0.125f;
                if (need_mask) {
                    int col = kt * 64 + nt * 8 + (lane & 3) * 2 + (c & 1);
                    int row = r0g + (c >> 1) * 8;
                    if (col > row) val = -1e30f;
                }
                s[nt][c] = val;
            }

        // online softmax
        float mx0 = -1e30f, mx1 = -1e30f;
#pragma unroll
        for (int nt = 0; nt < 8; nt++) {
            mx0 = fmaxf(mx0, fmaxf(s[nt][0], s[nt][1]));
            mx1 = fmaxf(mx1, fmaxf(s[nt][2], s[nt][3]));
        }
        mx0 = fmaxf(mx0, __shfl_xor_sync(0xffffffffu, mx0, 1));
        mx0 = fmaxf(mx0, __shfl_xor_sync(0xffffffffu, mx0, 2));
        mx1 = fmaxf(mx1, __shfl_xor_sync(0xffffffffu, mx1, 1));
        mx1 = fmaxf(mx1, __shfl_xor_sync(0xffffffffu, mx1, 2));
        float nm0 = fmaxf(m0, mx0), nm1 = fmaxf(m1, mx1);
        float cr0 = __expf(m0 - nm0), cr1 = __expf(m1 - nm1);
        m0 = nm0; m1 = nm1;
        float rs0 = 0.0f, rs1 = 0.0f;
#pragma unroll
        for (int nt = 0; nt < 8; nt++) {
            s[nt][0] = __expf(s[nt][0] - nm0);
            s[nt][1] = __expf(s[nt][1] - nm0);
            s[nt][2] = __expf(s[nt][2] - nm1);
            s[nt][3] = __expf(s[nt][3] - nm1);
            rs0 += s[nt][0] + s[nt][1];
            rs1 += s[nt][2] + s[nt][3];
        }
        rs0 += __shfl_xor_sync(0xffffffffu, rs0, 1);
        rs0 += __shfl_xor_sync(0xffffffffu, rs0, 2);
        rs1 += __shfl_xor_sync(0xffffffffu, rs1, 1);
        rs1 += __shfl_xor_sync(0xffffffffu, rs1, 2);
        l0 = l0 * cr0 + rs0;
        l1 = l1 * cr1 + rs1;
#pragma unroll
        for (int nt = 0; nt < 8; nt++) {
            oacc[nt][0] *= cr0; oacc[nt][1] *= cr0;
            oacc[nt][2] *= cr1; oacc[nt][3] *= cr1;
        }

        // O += P V
#pragma unroll
        for (int j = 0; j < 4; j++) {
            uint32_t ph[4], pl[4];
            split_pack(s[2 * j][0], s[2 * j][1], ph[0], pl[0]);
            split_pack(s[2 * j][2], s[2 * j][3], ph[1], pl[1]);
            split_pack(s[2 * j + 1][0], s[2 * j + 1][1], ph[2], pl[2]);
            split_pack(s[2 * j + 1][2], s[2 * j + 1][3], ph[3], pl[3]);
#pragma unroll
            for (int nt = 0; nt < 8; nt++) {
                uint32_t a = stb + 2 * KVBUF + (uint32_t)((j * 16 + (lane & 15)) * FROWB + nt * 16);
                uint32_t vh2[2], vl2[2];
                ldsm2t(vh2, a);
                ldsm2t(vl2, a + KVBUF);
                mma16816(oacc[nt], ph, vh2);
                mma16816(oacc[nt], ph, vl2);
                mma16816(oacc[nt], pl, vh2);
            }
        }
        __syncthreads();   // all reads of this stage done before it is refilled
    }

    // epilogue
    const float inv0 = 1.0f / l0, inv1 = 1.0f / l1;
    const int row0 = q0 + wid * 16 + (lane >> 2);
    const int colb = (lane & 3) * 2;
#pragma unroll
    for (int nt = 0; nt < 8; nt++) {
        size_t p0 = base + (size_t)row0 * DM + nt * 8 + colb;
        size_t p1 = p0 + 8 * (size_t)DM;
        uint32_t hp, lp;
        split_pack(oacc[nt][0] * inv0, oacc[nt][1] * inv0, hp, lp);
        *reinterpret_cast<uint32_t*>(oh + p0) = hp;
        *reinterpret_cast<uint32_t*>(ol + p0) = lp;
        split_pack(oacc[nt][2] * inv1, oacc[nt][3] * inv1, hp, lp);
        *reinterpret_cast<uint32_t*>(oh + p1) = hp;
        *reinterpret_cast<uint32_t*>(ol + p1) = lp;
    }
}

// ---------------- launch ----------------
extern "C" void kernel_launch(void* const* d_in, const int* in_sizes, int n_in,
                              void* d_out, int out_size) {
    const float* x  = (const float*)d_in[0];
    const float* W[4] = {(const float*)d_in[1], (const float*)d_in[2],
                         (const float*)d_in[3], (const float*)d_in[4]};
    float* out = (float*)d_out;

    __nv_bfloat16 *qhi, *qlo, *khi, *klo, *vhi, *vlo, *ahi, *alo, *xhi, *xlo, *whi, *wlo;
    cudaGetSymbolAddress((void**)&qhi, g_qhi); cudaGetSymbolAddress((void**)&qlo, g_qlo);
    cudaGetSymbolAddress((void**)&khi, g_khi); cudaGetSymbolAddress((void**)&klo, g_klo);
    cudaGetSymbolAddress((void**)&vhi, g_vhi); cudaGetSymbolAddress((void**)&vlo, g_vlo);
    cudaGetSymbolAddress((void**)&ahi, g_ahi); cudaGetSymbolAddress((void**)&alo, g_alo);
    cudaGetSymbolAddress((void**)&xhi, g_xhi); cudaGetSymbolAddress((void**)&xlo, g_xlo);
    cudaGetSymbolAddress((void**)&whi, g_whi); cudaGetSymbolAddress((void**)&wlo, g_wlo);

    cudaFuncSetAttribute(gemm_mma<true>,  cudaFuncAttributeMaxDynamicSharedMemorySize, GSMEM);
    cudaFuncSetAttribute(gemm_mma<false>, cudaFuncAttributeMaxDynamicSharedMemorySize, GSMEM);
    cudaFuncSetAttribute(flash_mma, cudaFuncAttributeMaxDynamicSharedMemorySize, FSMEM2);

    // fused split of all 5 fp32 inputs
    split5_kernel<<<8192, 256>>>(x, W[0], W[1], W[2], W[3], xhi, xlo, whi, wlo);

    dim3 gGrid(DM / 128, MROWS / 128);   // (8, 32)
    gemm_mma<true><<<gGrid, 256, GSMEM>>>(xhi, xlo, whi + 0 * (size_t)NELEM_W, wlo + 0 * (size_t)NELEM_W,
                                          nullptr, qhi, qlo, MROWS, DM, DM);
    gemm_mma<true><<<gGrid, 256, GSMEM>>>(xhi, xlo, whi + 1 * (size_t)NELEM_W, wlo + 1 * (size_t)NELEM_W,
                                          nullptr, khi, klo, MROWS, DM, DM);
    gemm_mma<true><<<gGrid, 256, GSMEM>>>(xhi, xlo, whi + 2 * (size_t)NELEM_W, wlo + 2 * (size_t)NELEM_W,
                                          nullptr, vhi, vlo, MROWS, DM, DM);

    dim3 fGrid(TT / FBR, BB * NH);       // (16, 32)
    flash_mma<<<fGrid, 256, FSMEM2>>>(qhi, qlo, khi, klo, vhi, vlo, ahi, alo);

    gemm_mma<false><<<gGrid, 256, GSMEM>>>(ahi, alo, whi + 3 * (size_t)NELEM_W, wlo + 3 * (size_t)NELEM_W,
                                           out, nullptr, nullptr, MROWS, DM, DM);
}